// round 8
// baseline (speedup 1.0000x reference)
#include <cuda_runtime.h>

#define NUM_EDGES   500000
#define GS2         20000
#define SIZE1       80000
#define SIZE2       80000
#define BATCH       8
#define CAP         96           // bucket capacity per dst (Poisson(25) max ~55)

// Batch-minor copy of x: xt[s*8 + b]. 2.56 MB.
__device__ float  g_xt[SIZE1 * BATCH];
__device__ int    g_count[GS2];
// Per-dst buckets: precomputed v blocks (4 float4 rows per edge) + src4.
__device__ float4 g_bucket_v[(size_t)GS2 * CAP * 4];   // ~123 MB
__device__ int    g_bucket_s[GS2 * CAP];               // ~7.7 MB

// ---------------------------------------------------------------------------
// K1: transpose x[b,s] -> xt[s,b] (2 threads per s, 4 batches each);
// zero per-dst counters; zero kl tail of out.
// ---------------------------------------------------------------------------
__global__ void __launch_bounds__(256)
prep_kernel(const float* __restrict__ x, float* __restrict__ out, int out_size) {
    int idx = blockIdx.x * blockDim.x + threadIdx.x;
    if (idx < SIZE1 * 2) {
        int s = idx >> 1;
        int h = idx & 1;           // batch half: 0 -> b=0..3, 1 -> b=4..7
        float4 v;
        v.x = __ldg(&x[(4 * h + 0) * SIZE1 + s]);
        v.y = __ldg(&x[(4 * h + 1) * SIZE1 + s]);
        v.z = __ldg(&x[(4 * h + 2) * SIZE1 + s]);
        v.w = __ldg(&x[(4 * h + 3) * SIZE1 + s]);
        *reinterpret_cast<float4*>(g_xt + (size_t)s * 8 + 4 * h) = v;
    }
    if (idx < GS2) g_count[idx] = 0;
    if (idx == 0) {
        for (int k = BATCH * SIZE2; k < out_size; k++) out[k] = 0.0f;  // kl = 0
    }
}

// ---------------------------------------------------------------------------
// K2: bin edges by dst, fusing the value computation.
// 4 lanes per edge, 8 edges per warp. Lane (g,t) handles row i=t of edge
// e0+g. Weight loads are fully dense (contiguous 512B per warp instruction).
// Writes the edge's 4x4 v block (64B contiguous per group) + src4 into the
// dst's bucket.
// ---------------------------------------------------------------------------
__global__ void __launch_bounds__(256)
bin_kernel(const float4* __restrict__ w_mean4,
           const float4* __restrict__ w_lv4,
           const float4* __restrict__ eps_w4,
           const int* __restrict__ rows,
           const int* __restrict__ cols) {
    const unsigned FULL = 0xffffffffu;
    int lane = threadIdx.x & 31;
    int warp = (blockIdx.x * blockDim.x + threadIdx.x) >> 5;
    int e0 = warp * 8;
    if (e0 >= NUM_EDGES) return;   // NUM_EDGES % 8 == 0

    int t = lane & 3;              // row i within the 4x4 block
    int e = e0 + (lane >> 2);      // this group's edge

    // Dense weight loads: address = e0*64 + lane*16, contiguous across warp.
    float4 m  = __ldg(&w_mean4[(size_t)e0 * 4 + lane]);
    float4 lv = __ldg(&w_lv4 [(size_t)e0 * 4 + lane]);
    float4 ep = __ldg(&eps_w4[(size_t)e0 * 4 + lane]);
    float4 vo;
    vo.x = fmaf(ep.x, __expf(lv.x), m.x);
    vo.y = fmaf(ep.y, __expf(lv.y), m.y);
    vo.z = fmaf(ep.z, __expf(lv.z), m.z);
    vo.w = fmaf(ep.w, __expf(lv.w), m.w);

    // Indices + bucket slot: one lane per group, then broadcast.
    int pos = 0, d = 0, src4 = 0;
    if (t == 0) {
        d    = __ldg(&rows[(size_t)e * 16]) >> 2;   // dst
        src4 = __ldg(&cols[(size_t)e * 16]);        // src*4
        pos  = atomicAdd(&g_count[d], 1);
    }
    int gbase = lane & ~3;
    d    = __shfl_sync(FULL, d,    gbase);
    src4 = __shfl_sync(FULL, src4, gbase);
    pos  = __shfl_sync(FULL, pos,  gbase);

    if (pos < CAP) {
        size_t slot = (size_t)d * CAP + pos;
        g_bucket_v[slot * 4 + t] = vo;              // 64B contiguous per group
        if (t == 0) g_bucket_s[slot] = src4;
    }
}

// ---------------------------------------------------------------------------
// K3: gather. One warp per dst; 4 lanes per edge, 8 edges per iteration.
// Bucket reads are contiguous (dense); only the x-gather is scattered
// (one aligned 128B block per edge). No atomics; output written once.
// ---------------------------------------------------------------------------
__global__ void __launch_bounds__(256)
gather_kernel(const float* __restrict__ b_mean,
              const float* __restrict__ b_log_var,
              const float* __restrict__ eps_b,
              float* __restrict__ out) {
    const unsigned FULL = 0xffffffffu;
    int lane = threadIdx.x & 31;
    int d = blockIdx.x * 8 + (threadIdx.x >> 5);
    if (d >= GS2) return;

    int n = g_count[d];
    if (n > CAP) n = CAP;
    const float4* bv = g_bucket_v + (size_t)d * CAP * 4;
    const int*    bs = g_bucket_s + (size_t)d * CAP;

    const int t = lane & 3;      // batches 2t,2t+1 / owns v-row i=t
    const int g = lane >> 2;     // edge slot within iteration
    const int gbase = lane & ~3;

    // acc[j*2 + bb]: j = 0..3, batches 2t+bb
    float acc[8];
#pragma unroll
    for (int k = 0; k < 8; k++) acc[k] = 0.0f;

    for (int it = 0; it * 8 < n; it++) {
        int slot = g + it * 8;
        bool active = slot < n;
        int slot_c = active ? slot : 0;

        // v row t of this edge: contiguous 512B across the warp.
        float4 vo = __ldg(&bv[(size_t)slot_c * 4 + t]);
        if (!active) { vo.x = vo.y = vo.z = vo.w = 0.0f; }

        // src4 (broadcast load within group; 32B contiguous across warp)
        int src4 = __ldg(&bs[slot_c]);

        // x for batches 2t,2t+1, rows i=0..3 from the 128B block at src4*32B
        const float* xb = g_xt + (size_t)src4 * 8 + 2 * t;
        float2 xv[4];
#pragma unroll
        for (int i = 0; i < 4; i++)
            xv[i] = *reinterpret_cast<const float2*>(xb + i * 8);

#pragma unroll
        for (int i = 0; i < 4; i++) {
            float vix = __shfl_sync(FULL, vo.x, gbase + i);
            float viy = __shfl_sync(FULL, vo.y, gbase + i);
            float viz = __shfl_sync(FULL, vo.z, gbase + i);
            float viw = __shfl_sync(FULL, vo.w, gbase + i);
            acc[0] = fmaf(vix, xv[i].x, acc[0]);
            acc[1] = fmaf(vix, xv[i].y, acc[1]);
            acc[2] = fmaf(viy, xv[i].x, acc[2]);
            acc[3] = fmaf(viy, xv[i].y, acc[3]);
            acc[4] = fmaf(viz, xv[i].x, acc[4]);
            acc[5] = fmaf(viz, xv[i].y, acc[5]);
            acc[6] = fmaf(viw, xv[i].x, acc[6]);
            acc[7] = fmaf(viw, xv[i].y, acc[7]);
        }
    }

    // reduce the 8 edge slots
#pragma unroll
    for (int off = 4; off <= 16; off <<= 1) {
#pragma unroll
        for (int k = 0; k < 8; k++)
            acc[k] += __shfl_xor_sync(FULL, acc[k], off);
    }

    // bias for j = t, broadcast to all lanes
    int d4 = d * 4;
    float bias_own = fmaf(__ldg(&eps_b[d4 + t]), __expf(__ldg(&b_log_var[d4 + t])),
                          __ldg(&b_mean[d4 + t]));
    float bj0 = __shfl_sync(FULL, bias_own, 0);
    float bj1 = __shfl_sync(FULL, bias_own, 1);
    float bj2 = __shfl_sync(FULL, bias_own, 2);
    float bj3 = __shfl_sync(FULL, bias_own, 3);

    if (g == 0) {
        float4 o0, o1;
        o0.x = acc[0] + bj0; o0.y = acc[2] + bj1; o0.z = acc[4] + bj2; o0.w = acc[6] + bj3;
        o1.x = acc[1] + bj0; o1.y = acc[3] + bj1; o1.z = acc[5] + bj2; o1.w = acc[7] + bj3;
        *reinterpret_cast<float4*>(out + (size_t)(2 * t) * SIZE2 + d4) = o0;
        *reinterpret_cast<float4*>(out + (size_t)(2 * t + 1) * SIZE2 + d4) = o1;
    }
}

extern "C" void kernel_launch(void* const* d_in, const int* in_sizes, int n_in,
                              void* d_out, int out_size) {
    const float* x      = (const float*)d_in[0];
    const float* w_mean = (const float*)d_in[1];
    const float* w_lv   = (const float*)d_in[2];
    const float* b_mean = (const float*)d_in[3];
    const float* b_lv   = (const float*)d_in[4];
    const float* eps_w  = (const float*)d_in[5];
    const float* eps_b  = (const float*)d_in[6];
    const int*   rows   = (const int*)d_in[7];
    const int*   cols   = (const int*)d_in[8];
    float* out = (float*)d_out;

    prep_kernel<<<(SIZE1 * 2 + 255) / 256, 256>>>(x, out, out_size);

    // 8 edges per warp -> NUM_EDGES/8 warps
    bin_kernel<<<(NUM_EDGES / 8 * 32 + 255) / 256, 256>>>(
        (const float4*)w_mean, (const float4*)w_lv, (const float4*)eps_w,
        rows, cols);

    gather_kernel<<<(GS2 + 7) / 8, 256>>>(b_mean, b_lv, eps_b, out);
}

// round 13
// speedup vs baseline: 1.3139x; 1.3139x over previous
#include <cuda_runtime.h>

#define NUM_EDGES   500000
#define SIZE1       80000
#define SIZE2       80000
#define BATCH       8

// Batch-minor copy of x: xt[s*8 + b]. 2.56 MB, L2-resident during edge kernel.
__device__ float g_xt[SIZE1 * BATCH];

// ---------------------------------------------------------------------------
// K1 (fused prep): transpose x[b,s] -> xt[s,b] (2 threads/s, 4 batches each);
// init out (batch-major) with reparameterized bias; zero kl tail.
// ---------------------------------------------------------------------------
__global__ void __launch_bounds__(256)
prep_kernel(const float* __restrict__ x,
            const float* __restrict__ b_mean,
            const float* __restrict__ b_log_var,
            const float* __restrict__ eps_b,
            float* __restrict__ out, int out_size) {
    int idx = blockIdx.x * blockDim.x + threadIdx.x;

    if (idx < SIZE1 * 2) {
        int s = idx >> 1;
        int h = idx & 1;           // batch half: 0 -> b=0..3, 1 -> b=4..7
        float4 v;
        v.x = __ldg(&x[(4 * h + 0) * SIZE1 + s]);
        v.y = __ldg(&x[(4 * h + 1) * SIZE1 + s]);
        v.z = __ldg(&x[(4 * h + 2) * SIZE1 + s]);
        v.w = __ldg(&x[(4 * h + 3) * SIZE1 + s]);
        *reinterpret_cast<float4*>(g_xt + (size_t)s * 8 + 4 * h) = v;
    }

    const int total = BATCH * SIZE2;
    if (idx < total) {
        int r = idx % SIZE2;
        out[idx] = fmaf(__ldg(&eps_b[r]), __expf(__ldg(&b_log_var[r])), __ldg(&b_mean[r]));
    } else if (idx < out_size) {
        out[idx] = 0.0f;   // kl = 0
    }
}

// ---------------------------------------------------------------------------
// K2: edge kernel. 4 lanes per edge, 8 edges per warp.
// Lane (g, t): g = edge slot 0..7, t = 0..3.
//   - holds v row i=t of edge e0+g (dense cooperative weight load)
//   - accumulates output for batches 2t, 2t+1 (all j) via shfl of v rows
//   - issues 2 scattered red.v4 into batch planes 2t, 2t+1 (proven layout)
// ---------------------------------------------------------------------------
__global__ void __launch_bounds__(256)
spmm_edge_kernel(const float4* __restrict__ w_mean4,
                 const float4* __restrict__ w_lv4,
                 const float4* __restrict__ eps_w4,
                 const int* __restrict__ rows,
                 const int* __restrict__ cols,
                 float* __restrict__ out) {
    const unsigned FULL = 0xffffffffu;
    int lane = threadIdx.x & 31;
    int warp = (blockIdx.x * blockDim.x + threadIdx.x) >> 5;
    int e0 = warp * 8;
    if (e0 >= NUM_EDGES) return;       // NUM_EDGES % 8 == 0

    const int t = lane & 3;
    const int g = lane >> 2;
    const int gbase = lane & ~3;

    // Dense weight loads: addr = e0*64B + lane*16B, contiguous 512B per instr.
    float4 m  = __ldg(&w_mean4[(size_t)e0 * 4 + lane]);
    float4 lv = __ldg(&w_lv4 [(size_t)e0 * 4 + lane]);
    float4 ep = __ldg(&eps_w4[(size_t)e0 * 4 + lane]);
    float4 vo;                          // v row i=t of edge e0+g (across j)
    vo.x = fmaf(ep.x, __expf(lv.x), m.x);
    vo.y = fmaf(ep.y, __expf(lv.y), m.y);
    vo.z = fmaf(ep.z, __expf(lv.z), m.z);
    vo.w = fmaf(ep.w, __expf(lv.w), m.w);

    // Indices: lanes 0-7 load rows (dst*4), lanes 8-15 load cols (src*4).
    int idxv = 0;
    if (lane < 8)       idxv = __ldg(&rows[(size_t)(e0 + lane) * 16]);
    else if (lane < 16) idxv = __ldg(&cols[(size_t)(e0 + lane - 8) * 16]);
    int dst4 = __shfl_sync(FULL, idxv, g);
    int src4 = __shfl_sync(FULL, idxv, 8 + g);

    // x for batches 2t, 2t+1, rows i=0..3 from the 128B block at src4*32B.
    const float* xb = g_xt + (size_t)src4 * 8 + 2 * t;
    float2 xv[4];
#pragma unroll
    for (int i = 0; i < 4; i++)
        xv[i] = *reinterpret_cast<const float2*>(xb + i * 8);

    // acc[j*2 + bb]: output j = 0..3 for batches 2t+bb.
    float acc[8];
#pragma unroll
    for (int k = 0; k < 8; k++) acc[k] = 0.0f;

#pragma unroll
    for (int i = 0; i < 4; i++) {
        float vix = __shfl_sync(FULL, vo.x, gbase + i);   // v[i][0]
        float viy = __shfl_sync(FULL, vo.y, gbase + i);   // v[i][1]
        float viz = __shfl_sync(FULL, vo.z, gbase + i);   // v[i][2]
        float viw = __shfl_sync(FULL, vo.w, gbase + i);   // v[i][3]
        acc[0] = fmaf(vix, xv[i].x, acc[0]);
        acc[1] = fmaf(vix, xv[i].y, acc[1]);
        acc[2] = fmaf(viy, xv[i].x, acc[2]);
        acc[3] = fmaf(viy, xv[i].y, acc[3]);
        acc[4] = fmaf(viz, xv[i].x, acc[4]);
        acc[5] = fmaf(viz, xv[i].y, acc[5]);
        acc[6] = fmaf(viw, xv[i].x, acc[6]);
        acc[7] = fmaf(viw, xv[i].y, acc[7]);
    }

    // Scattered vector reductions into batch planes 2t and 2t+1.
    float* o0 = out + (size_t)(2 * t) * SIZE2 + dst4;
    float* o1 = o0 + SIZE2;
    asm volatile("red.global.add.v4.f32 [%0], {%1, %2, %3, %4};"
                 :: "l"(o0), "f"(acc[0]), "f"(acc[2]), "f"(acc[4]), "f"(acc[6])
                 : "memory");
    asm volatile("red.global.add.v4.f32 [%0], {%1, %2, %3, %4};"
                 :: "l"(o1), "f"(acc[1]), "f"(acc[3]), "f"(acc[5]), "f"(acc[7])
                 : "memory");
}

extern "C" void kernel_launch(void* const* d_in, const int* in_sizes, int n_in,
                              void* d_out, int out_size) {
    const float* x      = (const float*)d_in[0];
    const float* w_mean = (const float*)d_in[1];
    const float* w_lv   = (const float*)d_in[2];
    const float* b_mean = (const float*)d_in[3];
    const float* b_lv   = (const float*)d_in[4];
    const float* eps_w  = (const float*)d_in[5];
    const float* eps_b  = (const float*)d_in[6];
    const int*   rows   = (const int*)d_in[7];
    const int*   cols   = (const int*)d_in[8];
    float* out = (float*)d_out;

    int prep_n = out_size > SIZE1 * 2 ? out_size : SIZE1 * 2;
    prep_kernel<<<(prep_n + 255) / 256, 256>>>(x, b_mean, b_lv, eps_b, out, out_size);

    // 8 edges per warp -> NUM_EDGES/8 warps -> *4 threads per edge
    spmm_edge_kernel<<<(NUM_EDGES / 8 * 32 + 255) / 256, 256>>>(
        (const float4*)w_mean, (const float4*)w_lv, (const float4*)eps_w,
        rows, cols, out);
}

// round 14
// speedup vs baseline: 1.3911x; 1.0587x over previous
#include <cuda_runtime.h>

#define NUM_EDGES   500000
#define SIZE1       80000
#define SIZE2       80000
#define BATCH       8

// Batch-minor copy of x: xt[s*8 + b]. 2.56 MB, L2-resident during edge kernel.
__device__ float g_xt[SIZE1 * BATCH];

// Quad-packed accumulator scratch, 2 copies to spread atomic contention.
// q[copy][p][s][c] : p = b>>2 (2 planes), c = b&3. copy selected by edge parity.
// Flat: copy*(2*SIZE2*4) + p*(SIZE2*4) + s*4 + c.  Total 2*2.56MB = 5.12 MB.
#define QPLANE  (SIZE2 * 4)
#define QCOPY   (2 * QPLANE)
__device__ float g_q[2 * QCOPY];

// ---------------------------------------------------------------------------
// K1 (prep): zero scratch (float4); transpose x[b,s] -> xt[s,b].
// ---------------------------------------------------------------------------
__global__ void __launch_bounds__(256)
prep_kernel(const float* __restrict__ x) {
    int idx = blockIdx.x * blockDim.x + threadIdx.x;

    // zero scratch: 2*QCOPY floats = 320k float4
    if (idx < (2 * QCOPY) / 4) {
        reinterpret_cast<float4*>(g_q)[idx] = make_float4(0.f, 0.f, 0.f, 0.f);
    }

    if (idx < SIZE1 * 2) {
        int s = idx >> 1;
        int h = idx & 1;           // batch half: 0 -> b=0..3, 1 -> b=4..7
        float4 v;
        v.x = __ldg(&x[(4 * h + 0) * SIZE1 + s]);
        v.y = __ldg(&x[(4 * h + 1) * SIZE1 + s]);
        v.z = __ldg(&x[(4 * h + 2) * SIZE1 + s]);
        v.w = __ldg(&x[(4 * h + 3) * SIZE1 + s]);
        *reinterpret_cast<float4*>(g_xt + (size_t)s * 8 + 4 * h) = v;
    }
}

// ---------------------------------------------------------------------------
// K2: edge kernel. 4 lanes per edge, 8 edges per warp.
// Lane (g, t): g = edge slot 0..7, t = 0..3 = 2p + h, p = plane, h = j-half.
//   - v row i=t loaded cooperatively (dense 512B per warp instruction)
//   - accumulates batches 2t, 2t+1 for all j via shfl of v rows
//   - lane pairs swap halves so each lane emits 2 red.v4 of (c0..c3) for
//     j = 2h, 2h+1 into quad-packed scratch: 2 lines/edge instead of 8.
// ---------------------------------------------------------------------------
__global__ void __launch_bounds__(256)
spmm_edge_kernel(const float4* __restrict__ w_mean4,
                 const float4* __restrict__ w_lv4,
                 const float4* __restrict__ eps_w4,
                 const int* __restrict__ rows,
                 const int* __restrict__ cols) {
    const unsigned FULL = 0xffffffffu;
    int lane = threadIdx.x & 31;
    int warp = (blockIdx.x * blockDim.x + threadIdx.x) >> 5;
    int e0 = warp * 8;
    if (e0 >= NUM_EDGES) return;       // NUM_EDGES % 8 == 0

    const int t = lane & 3;
    const int g = lane >> 2;
    const int gbase = lane & ~3;
    const int h = t & 1;               // j-half
    const int p = t >> 1;              // quad plane

    // Dense weight loads: addr = e0*64B + lane*16B, contiguous 512B per instr.
    float4 m  = __ldg(&w_mean4[(size_t)e0 * 4 + lane]);
    float4 lv = __ldg(&w_lv4 [(size_t)e0 * 4 + lane]);
    float4 ep = __ldg(&eps_w4[(size_t)e0 * 4 + lane]);
    float4 vo;                          // v row i=t of edge e0+g (across j)
    vo.x = fmaf(ep.x, __expf(lv.x), m.x);
    vo.y = fmaf(ep.y, __expf(lv.y), m.y);
    vo.z = fmaf(ep.z, __expf(lv.z), m.z);
    vo.w = fmaf(ep.w, __expf(lv.w), m.w);

    // Indices: lanes 0-7 load rows (dst*4), lanes 8-15 load cols (src*4).
    int idxv = 0;
    if (lane < 8)       idxv = __ldg(&rows[(size_t)(e0 + lane) * 16]);
    else if (lane < 16) idxv = __ldg(&cols[(size_t)(e0 + lane - 8) * 16]);
    int dst4 = __shfl_sync(FULL, idxv, g);
    int src4 = __shfl_sync(FULL, idxv, 8 + g);

    // x for batches 2t, 2t+1, rows i=0..3 from the 128B block at src4*32B.
    const float* xb = g_xt + (size_t)src4 * 8 + 2 * t;
    float2 xv[4];
#pragma unroll
    for (int i = 0; i < 4; i++)
        xv[i] = *reinterpret_cast<const float2*>(xb + i * 8);

    // acc[j*2 + bb]: output j = 0..3 for batches 2t+bb  (c = 2t+bb mod 4).
    float acc[8];
#pragma unroll
    for (int k = 0; k < 8; k++) acc[k] = 0.0f;

#pragma unroll
    for (int i = 0; i < 4; i++) {
        float vix = __shfl_sync(FULL, vo.x, gbase + i);   // v[i][0]
        float viy = __shfl_sync(FULL, vo.y, gbase + i);   // v[i][1]
        float viz = __shfl_sync(FULL, vo.z, gbase + i);   // v[i][2]
        float viw = __shfl_sync(FULL, vo.w, gbase + i);   // v[i][3]
        acc[0] = fmaf(vix, xv[i].x, acc[0]);
        acc[1] = fmaf(vix, xv[i].y, acc[1]);
        acc[2] = fmaf(viy, xv[i].x, acc[2]);
        acc[3] = fmaf(viy, xv[i].y, acc[3]);
        acc[4] = fmaf(viz, xv[i].x, acc[4]);
        acc[5] = fmaf(viz, xv[i].y, acc[5]);
        acc[6] = fmaf(viw, xv[i].x, acc[6]);
        acc[7] = fmaf(viw, xv[i].y, acc[7]);
    }

    // Pair swap (xor 1): send the j-half this lane doesn't own.
    // h==0 lane keeps j=0,1 (its c = 0,1), needs partner's j=0,1 (c = 2,3).
    // h==1 lane keeps j=2,3 (its c = 2,3), needs partner's j=2,3 (c = 0,1).
    float s0 = h ? acc[0] : acc[4];
    float s1 = h ? acc[1] : acc[5];
    float s2 = h ? acc[2] : acc[6];
    float s3 = h ? acc[3] : acc[7];
    float r0 = __shfl_xor_sync(FULL, s0, 1);
    float r1 = __shfl_xor_sync(FULL, s1, 1);
    float r2 = __shfl_xor_sync(FULL, s2, 1);
    float r3 = __shfl_xor_sync(FULL, s3, 1);

    // Assemble (c0,c1,c2,c3) vectors for j = 2h and 2h+1.
    float a0x = h ? r0 : acc[0];
    float a0y = h ? r1 : acc[1];
    float a0z = h ? acc[4] : r0;
    float a0w = h ? acc[5] : r1;
    float a1x = h ? r2 : acc[2];
    float a1y = h ? r3 : acc[3];
    float a1z = h ? acc[6] : r2;
    float a1w = h ? acc[7] : r3;

    // Scratch base: copy by edge parity, plane p, rows dst4+2h, dst4+2h+1.
    int e = e0 + g;
    float* qb = g_q + (size_t)(e & 1) * QCOPY + (size_t)p * QPLANE
              + (size_t)(dst4 + 2 * h) * 4;
    asm volatile("red.global.add.v4.f32 [%0], {%1, %2, %3, %4};"
                 :: "l"(qb), "f"(a0x), "f"(a0y), "f"(a0z), "f"(a0w)
                 : "memory");
    asm volatile("red.global.add.v4.f32 [%0], {%1, %2, %3, %4};"
                 :: "l"(qb + 4), "f"(a1x), "f"(a1y), "f"(a1z), "f"(a1w)
                 : "memory");
}

// ---------------------------------------------------------------------------
// K3 (finalize): out[b*SIZE2 + s] = qA + qB + bias(s); zero kl tail.
// Scratch reads are L2-resident; writes fully coalesced.
// ---------------------------------------------------------------------------
__global__ void __launch_bounds__(256)
finalize_kernel(const float* __restrict__ b_mean,
                const float* __restrict__ b_log_var,
                const float* __restrict__ eps_b,
                float* __restrict__ out, int out_size) {
    int idx = blockIdx.x * blockDim.x + threadIdx.x;
    const int total = BATCH * SIZE2;
    if (idx < total) {
        int b = idx / SIZE2;
        int s = idx - b * SIZE2;
        int off = (b >> 2) * QPLANE + s * 4 + (b & 3);
        float acc = g_q[off] + g_q[QCOPY + off];
        out[idx] = acc + fmaf(__ldg(&eps_b[s]), __expf(__ldg(&b_log_var[s])),
                              __ldg(&b_mean[s]));
    } else if (idx < out_size) {
        out[idx] = 0.0f;   // kl = 0
    }
}

extern "C" void kernel_launch(void* const* d_in, const int* in_sizes, int n_in,
                              void* d_out, int out_size) {
    const float* x      = (const float*)d_in[0];
    const float* w_mean = (const float*)d_in[1];
    const float* w_lv   = (const float*)d_in[2];
    const float* b_mean = (const float*)d_in[3];
    const float* b_lv   = (const float*)d_in[4];
    const float* eps_w  = (const float*)d_in[5];
    const float* eps_b  = (const float*)d_in[6];
    const int*   rows   = (const int*)d_in[7];
    const int*   cols   = (const int*)d_in[8];
    float* out = (float*)d_out;

    int prep_n = (2 * QCOPY) / 4;                      // 320k zeroing threads
    if (prep_n < SIZE1 * 2) prep_n = SIZE1 * 2;
    prep_kernel<<<(prep_n + 255) / 256, 256>>>(x);

    spmm_edge_kernel<<<(NUM_EDGES / 8 * 32 + 255) / 256, 256>>>(
        (const float4*)w_mean, (const float4*)w_lv, (const float4*)eps_w,
        rows, cols);

    finalize_kernel<<<(out_size + 255) / 256, 256>>>(b_mean, b_lv, eps_b, out, out_size);
}